// round 6
// baseline (speedup 1.0000x reference)
#include <cuda_runtime.h>

// ROICrop: bilinear crop of 1024 ROIs from (4,256,200,304) fp32 source into
// (1024,256,14,14) fp32 output. KEEP_AR (AR=1) + 10% extend ROI adjustment.
//
// R6 = R5 resubmitted after a broker/container flake (kernel re-audited:
// all LDG.128 are 16B-aligned, all accesses in bounds, no trap possible).
//
// R5 theory: R4 was L1tex-wavefront-bound (L1 81.9%, DRAM 36.5%, issue
// 20.6%). The two x-taps per row are adjacent (x1i = x0+1), so the two
// LDG.32s per row touch the same 128B line set but pay L1 wavefronts twice.
// Merge them: one aligned LDG.128 at xq = x0 & ~3 (always covers x0 and,
// unless x0&3==3, x0+1) plus a predicated scalar fixup load of column xq+4
// for sel==3 lanes. 4 scattered loads/channel -> 2 vector + 2 sparse.
// Alignment: row stride 304 floats (1216B % 16 == 0), channel/image strides
// 16B multiples, xq multiple of 4 floats -> 16B aligned. Bounds: xq+3 <= 303
// always; fixup xq+4 <= 300 whenever taken (requires x0 <= 299).
//
// Kept from R4 (the win): 1D grid of 8 channel bands x 1024 ROIs (roi
// fastest-varying -> each wave's ~31MB channel band is L2-resident, source
// DRAM reads ~ one pass), 224 threads = pixel per thread, streaming stores.

#define SRC_C 256
#define SRC_H 200
#define SRC_W 304
#define SRC_HW (SRC_H * SRC_W)
#define OH 14
#define OW 14
#define OPIX (OH * OW)
#define C_BANDS 8
#define C_PER_BAND (SRC_C / C_BANDS)   // 32

__global__ __launch_bounds__(224, 8) void ROICrop_kernel(
    const float* __restrict__ src,
    const float* __restrict__ rois,
    float* __restrict__ out,
    int n_rois)
{
    const int bid = blockIdx.x;
    const int roi  = bid % n_rois;          // fastest-varying: wave = one band
    const int band = bid / n_rois;
    const int c0 = band * C_PER_BAND;
    const int p = threadIdx.x;
    if (p >= OPIX) return;

    const int oy = p / OW;
    const int ox = p - oy * OW;

    // ---- load + adjust ROI (redundant per-thread; broadcast loads) ----
    const float* r = rois + roi * 5;
    const int b = (int)r[0];
    float x1 = r[1], y1 = r[2], x2 = r[3], y2 = r[4];

    // keep-aspect-ratio, AR = OW/OH = 1
    {
        const float h = y2 - y1 + 1.0f;
        const float w = x2 - x1 + 1.0f;
        const float ew = (h - w) * 0.5f;     // (h*AR - w)/2 with AR=1
        if (ew > 0.0f) {
            x1 -= ew; x2 += ew;
        } else {
            const float eh = (w - h) * 0.5f; // (w/AR - h)/2
            y1 -= eh; y2 += eh;
        }
    }
    // extend ratio 0.1
    {
        const float dx = (x2 - x1 + 1.0f) * 0.05f;
        const float dy = (y2 - y1 + 1.0f) * 0.05f;
        x1 -= dx; x2 += dx;
        y1 -= dy; y2 += dy;
    }

    // ---- per-pixel sample position ----
    const float ty = (float)oy / (float)(OH - 1);
    const float tx = (float)ox / (float)(OW - 1);
    float ys = y1 + (y2 - y1) * ty;
    float xs = x1 + (x2 - x1) * tx;
    ys = fminf(fmaxf(ys, 0.0f), (float)(SRC_H - 1));
    xs = fminf(fmaxf(xs, 0.0f), (float)(SRC_W - 1));

    const float y0f = floorf(ys);
    const float x0f = floorf(xs);
    const float wy = ys - y0f;
    const float wx = xs - x0f;
    const int y0 = (int)y0f;
    const int x0 = (int)x0f;
    const int y1i = min(y0 + 1, SRC_H - 1);
    const int x1i = min(x0 + 1, SRC_W - 1);

    const float w00 = (1.0f - wy) * (1.0f - wx);
    const float w01 = (1.0f - wy) * wx;
    const float w10 = wy * (1.0f - wx);
    const float w11 = wy * wx;

    // vectorized tap addressing
    const int xq  = x0 & ~3;          // 16B-aligned column group covering x0
    const int sel = x0 & 3;           // which element of the float4 is x0
    const bool fix = (sel == 3) && (x1i > x0);  // x0+1 falls in next group
    const int rowA = y0  * SRC_W + xq;
    const int rowB = y1i * SRC_W + xq;

    const float* base = src + (size_t)b * SRC_C * SRC_HW + (size_t)c0 * SRC_HW;
    float* outp = out + (size_t)roi * SRC_C * OPIX + (size_t)c0 * OPIX + p;

    // ---- channel-band loop: 2 vector loads + 2 predicated fixups ----
#pragma unroll 4
    for (int c = 0; c < C_PER_BAND; ++c) {
        const float* s = base + (size_t)c * SRC_HW;
        const float4 qa = __ldg((const float4*)(s + rowA));
        const float4 qb = __ldg((const float4*)(s + rowB));
        float ea = 0.0f, eb = 0.0f;
        if (fix) {
            ea = __ldg(s + rowA + 4);
            eb = __ldg(s + rowB + 4);
        }
        // select taps (sel is loop-invariant; SELs, no dynamic indexing)
        const float a0 = sel == 0 ? qa.x : sel == 1 ? qa.y : sel == 2 ? qa.z : qa.w;
        const float a1 = sel == 0 ? qa.y : sel == 1 ? qa.z : sel == 2 ? qa.w
                                  : (fix ? ea : qa.w);   // x1i==x0 clamp case
        const float b0 = sel == 0 ? qb.x : sel == 1 ? qb.y : sel == 2 ? qb.z : qb.w;
        const float b1 = sel == 0 ? qb.y : sel == 1 ? qb.z : sel == 2 ? qb.w
                                  : (fix ? eb : qb.w);

        const float v = w00 * a0 + w01 * a1 + w10 * b0 + w11 * b1;
        __stcs(outp + (size_t)c * OPIX, v);
    }
}

extern "C" void kernel_launch(void* const* d_in, const int* in_sizes, int n_in,
                              void* d_out, int out_size)
{
    const float* src  = (const float*)d_in[0];
    const float* rois = (const float*)d_in[1];
    float* out = (float*)d_out;

    int n_rois = in_sizes[1] / 5;   // 1024
    if (n_rois < 1) n_rois = 1;
    ROICrop_kernel<<<n_rois * C_BANDS, 224>>>(src, rois, out, n_rois);
}

// round 8
// speedup vs baseline: 1.2158x; 1.2158x over previous
#include <cuda_runtime.h>

// ROICrop: bilinear crop of 1024 ROIs from (4,256,200,304) fp32 source into
// (1024,256,14,14) fp32 output. KEEP_AR (AR=1) + 10% extend ROI adjustment.
//
// R8 = R7 resubmitted verbatim after a broker flake (precedent: R5 failed the
// same way and its identical resubmit R6 ran fine; kernel re-audited: scalar
// loads only, all in bounds, same 1D launch as the passing R4).
//
// R7 theory: R4 (best, 143.8us) is L1-port-bound (81.9%) with exposed L2
// latency — 32-reg cap (from the 8-blocks/SM bound) allows only ~5 loads in
// flight per thread. Lower the occupancy bound to 6 blocks/SM (48-reg
// budget) and batch the channel loop by 4 with all 16 tap loads issued
// before any FMA: 1344 thr/SM x ~16 outstanding >> 1792 x ~5, so scattered-
// tap L2 latency is hidden and the L1 port saturates.
//
// Kept from R4 (the win): 1D grid, 8 channel bands x 1024 ROIs with roi
// fastest-varying (wave ~= one ~31MB L2-resident channel band of all 4
// images -> source DRAM reads ~ one pass), pixel-per-thread, streaming
// stores so the 205MB output doesn't evict the band.

#define SRC_C 256
#define SRC_H 200
#define SRC_W 304
#define SRC_HW (SRC_H * SRC_W)
#define OH 14
#define OW 14
#define OPIX (OH * OW)
#define C_BANDS 8
#define C_PER_BAND (SRC_C / C_BANDS)   // 32

__global__ __launch_bounds__(224, 6) void ROICrop_kernel(
    const float* __restrict__ src,
    const float* __restrict__ rois,
    float* __restrict__ out,
    int n_rois)
{
    const int bid = blockIdx.x;
    const int roi  = bid % n_rois;          // fastest-varying: wave = one band
    const int band = bid / n_rois;
    const int c0 = band * C_PER_BAND;
    const int p = threadIdx.x;
    if (p >= OPIX) return;

    const int oy = p / OW;
    const int ox = p - oy * OW;

    // ---- load + adjust ROI (redundant per-thread; broadcast loads) ----
    const float* r = rois + roi * 5;
    const int b = (int)r[0];
    float x1 = r[1], y1 = r[2], x2 = r[3], y2 = r[4];

    // keep-aspect-ratio, AR = OW/OH = 1
    {
        const float h = y2 - y1 + 1.0f;
        const float w = x2 - x1 + 1.0f;
        const float ew = (h - w) * 0.5f;     // (h*AR - w)/2 with AR=1
        if (ew > 0.0f) {
            x1 -= ew; x2 += ew;
        } else {
            const float eh = (w - h) * 0.5f; // (w/AR - h)/2
            y1 -= eh; y2 += eh;
        }
    }
    // extend ratio 0.1
    {
        const float dx = (x2 - x1 + 1.0f) * 0.05f;
        const float dy = (y2 - y1 + 1.0f) * 0.05f;
        x1 -= dx; x2 += dx;
        y1 -= dy; y2 += dy;
    }

    // ---- per-pixel sample position ----
    const float ty = (float)oy / (float)(OH - 1);
    const float tx = (float)ox / (float)(OW - 1);
    float ys = y1 + (y2 - y1) * ty;
    float xs = x1 + (x2 - x1) * tx;
    ys = fminf(fmaxf(ys, 0.0f), (float)(SRC_H - 1));
    xs = fminf(fmaxf(xs, 0.0f), (float)(SRC_W - 1));

    const float y0f = floorf(ys);
    const float x0f = floorf(xs);
    const float wy = ys - y0f;
    const float wx = xs - x0f;
    const int y0 = (int)y0f;
    const int x0 = (int)x0f;
    const int y1i = min(y0 + 1, SRC_H - 1);
    const int x1i = min(x0 + 1, SRC_W - 1);

    const int o00 = y0  * SRC_W + x0;
    const int o01 = y0  * SRC_W + x1i;
    const int o10 = y1i * SRC_W + x0;
    const int o11 = y1i * SRC_W + x1i;

    const float w00 = (1.0f - wy) * (1.0f - wx);
    const float w01 = (1.0f - wy) * wx;
    const float w10 = wy * (1.0f - wx);
    const float w11 = wy * wx;

    const float* base = src + (size_t)b * SRC_C * SRC_HW + (size_t)c0 * SRC_HW;
    float* outp = out + (size_t)roi * SRC_C * OPIX + (size_t)c0 * OPIX + p;

    // ---- channel loop in 4-channel batches: 16 loads in flight, then FMAs ----
#pragma unroll
    for (int c = 0; c < C_PER_BAND; c += 4) {
        const float* s0 = base + (size_t)(c + 0) * SRC_HW;
        const float* s1 = base + (size_t)(c + 1) * SRC_HW;
        const float* s2 = base + (size_t)(c + 2) * SRC_HW;
        const float* s3 = base + (size_t)(c + 3) * SRC_HW;

        float t00a = __ldg(s0 + o00), t01a = __ldg(s0 + o01),
              t10a = __ldg(s0 + o10), t11a = __ldg(s0 + o11);
        float t00b = __ldg(s1 + o00), t01b = __ldg(s1 + o01),
              t10b = __ldg(s1 + o10), t11b = __ldg(s1 + o11);
        float t00c = __ldg(s2 + o00), t01c = __ldg(s2 + o01),
              t10c = __ldg(s2 + o10), t11c = __ldg(s2 + o11);
        float t00d = __ldg(s3 + o00), t01d = __ldg(s3 + o01),
              t10d = __ldg(s3 + o10), t11d = __ldg(s3 + o11);

        const float va = w00 * t00a + w01 * t01a + w10 * t10a + w11 * t11a;
        const float vb = w00 * t00b + w01 * t01b + w10 * t10b + w11 * t11b;
        const float vc = w00 * t00c + w01 * t01c + w10 * t10c + w11 * t11c;
        const float vd = w00 * t00d + w01 * t01d + w10 * t10d + w11 * t11d;

        __stcs(outp + (size_t)(c + 0) * OPIX, va);
        __stcs(outp + (size_t)(c + 1) * OPIX, vb);
        __stcs(outp + (size_t)(c + 2) * OPIX, vc);
        __stcs(outp + (size_t)(c + 3) * OPIX, vd);
    }
}

extern "C" void kernel_launch(void* const* d_in, const int* in_sizes, int n_in,
                              void* d_out, int out_size)
{
    const float* src  = (const float*)d_in[0];
    const float* rois = (const float*)d_in[1];
    float* out = (float*)d_out;

    int n_rois = in_sizes[1] / 5;   // 1024
    if (n_rois < 1) n_rois = 1;
    ROICrop_kernel<<<n_rois * C_BANDS, 224>>>(src, rois, out, n_rois);
}